// round 16
// baseline (speedup 1.0000x reference)
#include <cuda_runtime.h>
#include <cuda_bf16.h>
#include <cuda_fp16.h>
#include <math.h>
#include <stdint.h>

#define BB   8
#define LL   1024
#define HW   1024
#define HID  512
#define NH   8
#define DH   64

// fp16 tiled-swizzled GEMM operands: [tile (row>>7)*8 + (k>>6)][128x64 SW128 16KB]
__device__ __half g_kin_f[BB*LL*HID];
__device__ __half g_vin_f[BB*LL*HID];
__device__ __half g_qt_f [BB*HW*HID];
__device__ __half g_wk_f[HID*HID];
__device__ __half g_wv_f[HID*HID];
__device__ __half g_wq_f[HID*HID];
__device__ __half g_wm_f[HID*HID];
__device__ __half g_ao_f[BB*HW*HID];    // tiled (out-proj B operand)
// head-separated swizzled attention operands:
// K/V: [b][h][ltile 0..15][64x64 fp16 SW128 8KB]; Q: [b][h][qtile 0..7][128x64 16KB]
__device__ __half g_kf2[BB*LL*HID];
__device__ __half g_vf2[BB*LL*HID];
__device__ __half g_qf2[BB*HW*HID];
__device__ unsigned char g_mask[BB*LL];

// ---------------- helpers ----------------
__device__ __forceinline__ uint32_t packh2(float a, float b)
{
    __half2 h = __floats2half2_rn(a, b);
    return *reinterpret_cast<uint32_t*>(&h);
}
__device__ __forceinline__ float fexp2f(float x)
{
    x = fmaxf(x, -126.0f);
    int   n = __float2int_rn(x);
    float f = x - (float)n;
    float p = 1.33336498e-3f;
    p = fmaf(p, f, 9.61817007e-3f);
    p = fmaf(p, f, 5.55041087e-2f);
    p = fmaf(p, f, 2.40226507e-1f);
    p = fmaf(p, f, 6.93147181e-1f);
    p = fmaf(p, f, 1.0f);
    return p * __int_as_float((n + 127) << 23);
}
__device__ __forceinline__ void ldsm4(uint32_t& r0, uint32_t& r1, uint32_t& r2, uint32_t& r3, uint32_t a)
{
    asm volatile("ldmatrix.sync.aligned.m8n8.x4.shared.b16 {%0,%1,%2,%3}, [%4];"
                 : "=r"(r0), "=r"(r1), "=r"(r2), "=r"(r3) : "r"(a));
}
__device__ __forceinline__ void ldsm4t(uint32_t& r0, uint32_t& r1, uint32_t& r2, uint32_t& r3, uint32_t a)
{
    asm volatile("ldmatrix.sync.aligned.m8n8.x4.trans.shared.b16 {%0,%1,%2,%3}, [%4];"
                 : "=r"(r0), "=r"(r1), "=r"(r2), "=r"(r3) : "r"(a));
}
__device__ __forceinline__ void mma16816h(float* d, const uint32_t* a, uint32_t b0, uint32_t b1)
{
    asm volatile("mma.sync.aligned.m16n8k16.row.col.f32.f16.f16.f32 "
                 "{%0,%1,%2,%3}, {%4,%5,%6,%7}, {%8,%9}, {%0,%1,%2,%3};"
                 : "+f"(d[0]), "+f"(d[1]), "+f"(d[2]), "+f"(d[3])
                 : "r"(a[0]), "r"(a[1]), "r"(a[2]), "r"(a[3]), "r"(b0), "r"(b1));
}
__device__ __forceinline__ uint32_t swz128(uint32_t o) { return o ^ ((o >> 3) & 0x70); }

__device__ __forceinline__ void mbar_init(uint32_t a, uint32_t c)
{ asm volatile("mbarrier.init.shared.b64 [%0], %1;" :: "r"(a), "r"(c) : "memory"); }
__device__ __forceinline__ void mbar_expect(uint32_t a, uint32_t bytes)
{ asm volatile("mbarrier.arrive.expect_tx.shared.b64 _, [%0], %1;" :: "r"(a), "r"(bytes) : "memory"); }
__device__ __forceinline__ void mbar_wait(uint32_t a, uint32_t par)
{
    asm volatile(
        "{\n\t.reg .pred P;\n"
        "W%=:\n\tmbarrier.try_wait.parity.acquire.cta.shared::cta.b64 P, [%0], %1, 0x989680;\n"
        "\t@P bra.uni D%=;\n\tbra.uni W%=;\nD%=:\n\t}"
        :: "r"(a), "r"(par) : "memory");
}
__device__ __forceinline__ void bulk_g2s(uint32_t dst, const void* src, uint32_t bytes, uint32_t mbar)
{
    asm volatile("cp.async.bulk.shared::cta.global.mbarrier::complete_tx::bytes [%0], [%1], %2, [%3];"
                 :: "r"(dst), "l"(src), "r"(bytes), "r"(mbar) : "memory");
}

// ---------------- fp32 [R][512] -> fp16 tiled-swizzled (core) ----------------
__device__ __forceinline__ void pack_one(const float* in, __half* o, int i)
{
    int row = i >> 6;
    int kc  = (i & 63) * 8;
    const float4* p = (const float4*)(in + (size_t)row * HID + kc);
    float4 a = p[0], b = p[1];
    uint32_t h0 = packh2(a.x, a.y), h1 = packh2(a.z, a.w);
    uint32_t h2 = packh2(b.x, b.y), h3 = packh2(b.z, b.w);
    uint32_t off = swz128((uint32_t)((row & 127) * 128 + (kc & 63) * 2));
    size_t base = ((size_t)(row >> 7) * 8 + (kc >> 6)) * 16384 + off;
    *(uint4*)((char*)o + base) = make_uint4(h0, h1, h2, h3);
}

// ---------------------------------------------------------------------------
// Fused preprocessing (verified R13)
// ---------------------------------------------------------------------------
__global__ __launch_bounds__(256)
void fused_pre(const float* __restrict__ q, const float* __restrict__ k,
               const float* __restrict__ v, const float* __restrict__ Wk,
               const float* __restrict__ Wv, const float* __restrict__ Wq,
               const float* __restrict__ Wm, const unsigned char* __restrict__ m)
{
    const int blk = blockIdx.x, tid = threadIdx.x;
    if (blk < 4096) {
        __shared__ float t[32][33];
        int bx = blk & 31, by = (blk >> 5) & 15, bz = blk >> 9;
        int tx = tid & 31, ty = tid >> 5;
        int hw0 = bx * 32, c0 = by * 32;
        const float* ip = q + ((long)bz * HID + c0) * HW + hw0;
#pragma unroll
        for (int j = 0; j < 32; j += 8)
            t[ty + j][tx] = ip[(long)(ty + j) * HW + tx];
        __syncthreads();
#pragma unroll
        for (int j = 0; j < 32; j += 8) {
            float vv = t[tx][ty + j];
            int rowg = bz * HW + hw0 + ty + j;
            int col  = c0 + tx;
            uint32_t off = swz128((uint32_t)((rowg & 127) * 128 + (col & 63) * 2));
            size_t base = ((size_t)(rowg >> 7) * 8 + (col >> 6)) * 16384 + off;
            *(__half*)((char*)g_qt_f + base) = __float2half_rn(vv);
        }
    } else if (blk < 8192) {
        int bb = blk - 4096;
        int i = (bb & 2047) * 256 + tid;
        if (bb < 2048) pack_one(k, g_kin_f, i);
        else           pack_one(v, g_vin_f, i);
    } else if (blk < 8704) {
        int bb = blk - 8192;
        int i = (bb & 127) * 256 + tid;
        int z = bb >> 7;
        if (z == 0)      pack_one(Wk, g_wk_f, i);
        else if (z == 1) pack_one(Wv, g_wv_f, i);
        else if (z == 2) pack_one(Wq, g_wq_f, i);
        else             pack_one(Wm, g_wm_f, i);
    } else {
        __shared__ int s_wide, s_bytes;
        if (tid == 0) { s_wide = 0; s_bytes = 0; }
        __syncthreads();
        int wide = 0, bytes = 0;
        for (int i = tid; i < BB*LL; i += 256) {
            unsigned char c = m[i];
            if (c > 1) wide = 1;
            else if (c != 0 && (i & 3) != 0) bytes = 1;
        }
        if (wide)  atomicOr(&s_wide, 1);
        if (bytes) atomicOr(&s_bytes, 1);
        __syncthreads();
        const bool is_u8 = (!s_wide) && s_bytes;
        int i = (blk - 8704) * 256 + tid;
        unsigned char vv;
        if (is_u8) vv = (m[i] != 0);
        else       vv = (((const int*)m)[i] != 0);
        g_mask[i] = vv;
    }
}

// ---------------------------------------------------------------------------
// fp16 single-term GEMM mainloop (verified R10-R15).
// ---------------------------------------------------------------------------
__device__ __forceinline__ void gemm_mainloop_h(
    const __half* A, const __half* B, size_t at, size_t bt,
    uint32_t sb, int tid, int lane, int wid, float acc[4][4][4])
{
    const int wm = (wid & 1) * 64, wn = (wid >> 1) * 32;
    const int arow = lane & 15, acol8 = (lane >> 4) * 8;
    const uint32_t F0 = 65536u, F1 = 65544u;

    if (tid == 0) { mbar_init(sb + F0, 1); mbar_init(sb + F1, 1); }
    __syncthreads();
    if (tid == 0) {
        mbar_expect(sb + F0, 32768u);
        bulk_g2s(sb,           A + at * 8192, 16384u, sb + F0);
        bulk_g2s(sb + 16384u,  B + bt * 8192, 16384u, sb + F0);
        mbar_expect(sb + F1, 32768u);
        bulk_g2s(sb + 32768u,  A + (at + 1) * 8192, 16384u, sb + F1);
        bulk_g2s(sb + 49152u,  B + (bt + 1) * 8192, 16384u, sb + F1);
    }
    for (int s = 0; s < 8; s++) {
        mbar_wait((s & 1) ? sb + F1 : sb + F0, (uint32_t)((s >> 1) & 1));
        uint32_t bb = sb + (uint32_t)(s & 1) * 32768u;
#pragma unroll
        for (int ks = 0; ks < 4; ks++) {
            const int kc = ks * 16 + acol8;
            uint32_t ah[4][4];
#pragma unroll
            for (int i = 0; i < 4; i++) {
                uint32_t off = swz128((uint32_t)(((wm + 16 * i + arow) << 7) + (kc << 1)));
                ldsm4(ah[i][0], ah[i][1], ah[i][2], ah[i][3], bb + off);
            }
#pragma unroll
            for (int jj = 0; jj < 2; jj++) {
                uint32_t bh[4];
                uint32_t off = swz128((uint32_t)(((wn + 16 * jj + arow) << 7) + (kc << 1)));
                ldsm4(bh[0], bh[1], bh[2], bh[3], bb + 16384u + off);
#pragma unroll
                for (int i = 0; i < 4; i++) {
                    mma16816h(acc[i][2*jj],   ah[i], bh[0], bh[2]);
                    mma16816h(acc[i][2*jj+1], ah[i], bh[1], bh[3]);
                }
            }
        }
        __syncthreads();
        if (tid == 0 && s + 2 < 8) {
            uint32_t full = (s & 1) ? sb + F1 : sb + F0;
            uint32_t base = sb + (uint32_t)(s & 1) * 32768u;
            mbar_expect(full, 32768u);
            bulk_g2s(base,           A + (at + s + 2) * 8192, 16384u, full);
            bulk_g2s(base + 16384u,  B + (bt + s + 2) * 8192, 16384u, full);
        }
    }
}

// ---- fused k/v/q projections (verified R13) ----
__global__ __launch_bounds__(256, 2)
void proj_gemm(const float* __restrict__ bk, const float* __restrict__ bv,
               const float* __restrict__ bq)
{
    extern __shared__ char smc[];
    const uint32_t sb = (uint32_t)__cvta_generic_to_shared(smc);
    const int tid = threadIdx.x, lane = tid & 31, wid = tid >> 5;
    const int m0 = blockIdx.y * 128, n0 = blockIdx.x * 128, z = blockIdx.z;

    const __half *A, *B;
    const float* bias;
    if (z == 0)      { A = g_kin_f; B = g_wk_f; bias = bk; }
    else if (z == 1) { A = g_vin_f; B = g_wv_f; bias = bv; }
    else             { A = g_qt_f;  B = g_wq_f; bias = bq; }

    float acc[4][4][4] = {};
    gemm_mainloop_h(A, B, (size_t)(m0 >> 7) * 8, (size_t)(n0 >> 7) * 8,
                    sb, tid, lane, wid, acc);

    const int wm = (wid & 1) * 64, wn = (wid >> 1) * 32;
    const int g = lane >> 2, lam = lane & 3;
#pragma unroll
    for (int i = 0; i < 4; i++) {
#pragma unroll
        for (int j = 0; j < 4; j++) {
            int row0 = m0 + wm + 16 * i + g;
            int col  = n0 + wn + 8 * j + 2 * lam;
            float b0 = bias[col], b1 = bias[col + 1];
            uint32_t p0 = packh2(acc[i][j][0] + b0, acc[i][j][1] + b1);
            uint32_t p1 = packh2(acc[i][j][2] + b0, acc[i][j][3] + b1);
            int hh = col >> 6, cin = col & 63;
            if (z < 2) {
                __half* dst = (z == 0) ? g_kf2 : g_vf2;
                int r1 = row0 + 8;
                size_t tb0 = (((size_t)(row0 >> 10) * 8 + hh) * 16 + ((row0 & 1023) >> 6)) * 8192;
                size_t tb1 = (((size_t)(r1 >> 10) * 8 + hh) * 16 + ((r1 & 1023) >> 6)) * 8192;
                *(uint32_t*)((char*)dst + tb0 + swz128((uint32_t)((row0 & 63) * 128 + cin * 2))) = p0;
                *(uint32_t*)((char*)dst + tb1 + swz128((uint32_t)((r1 & 63) * 128 + cin * 2)))   = p1;
            } else {
                int r1 = row0 + 8;
                size_t tb0 = (((size_t)(row0 >> 10) * 8 + hh) * 8 + ((row0 & 1023) >> 7)) * 16384;
                size_t tb1 = (((size_t)(r1 >> 10) * 8 + hh) * 8 + ((r1 & 1023) >> 7)) * 16384;
                *(uint32_t*)((char*)g_qf2 + tb0 + swz128((uint32_t)((row0 & 127) * 128 + cin * 2))) = p0;
                *(uint32_t*)((char*)g_qf2 + tb1 + swz128((uint32_t)((r1 & 127) * 128 + cin * 2)))   = p1;
            }
        }
    }
}

// ---- output projection (verified R13) ----
__global__ __launch_bounds__(256, 2)
void out_gemm(const float* __restrict__ bm, float* __restrict__ out)
{
    extern __shared__ char smc[];
    const uint32_t sb = (uint32_t)__cvta_generic_to_shared(smc);
    const int tid = threadIdx.x, lane = tid & 31, wid = tid >> 5;
    const int m0 = blockIdx.y * 128, n0 = blockIdx.x * 128, z = blockIdx.z;

    float acc[4][4][4] = {};
    gemm_mainloop_h(g_wm_f, g_ao_f,
                    (size_t)(m0 >> 7) * 8, (size_t)((z * HW + n0) >> 7) * 8,
                    sb, tid, lane, wid, acc);

    const int wm = (wid & 1) * 64, wn = (wid >> 1) * 32;
    const int g = lane >> 2, lam = lane & 3;
    float* cfp = out + (size_t)z * 512 * HW;
#pragma unroll
    for (int i = 0; i < 4; i++) {
#pragma unroll
        for (int j = 0; j < 4; j++) {
            int row0 = m0 + wm + 16 * i + g;
            int col  = n0 + wn + 8 * j + 2 * lam;
            float ba = bm[row0], bb2 = bm[row0 + 8];
            float v00 = fmaxf(acc[i][j][0] + ba, 0.f),  v01 = fmaxf(acc[i][j][1] + ba, 0.f);
            float v10 = fmaxf(acc[i][j][2] + bb2, 0.f), v11 = fmaxf(acc[i][j][3] + bb2, 0.f);
            *(float2*)&cfp[(size_t)row0 * HW + col]       = make_float2(v00, v01);
            *(float2*)&cfp[(size_t)(row0 + 8) * HW + col] = make_float2(v10, v11);
        }
    }
}

// ---------------------------------------------------------------------------
// Flash attention: fp16, Br=128, Bc=64, bulk loads, 2 CTAs/SM.
// Fixed-zero-max single-pass softmax (shift-invariant; scores bounded:
// s2 std ~0.29, max ~6 sigma ~1.7; fp16 P overflow needs s2 > 16 ~ 55 sigma).
// Correctness of this variant verified in R14 (rel_err 4.99e-4).
// ---------------------------------------------------------------------------
__global__ __launch_bounds__(256, 2)
void attn_kernel()
{
    extern __shared__ __align__(1024) uint32_t dsm[];
    __shared__ unsigned char s_maskAll[LL];
    const int tid = threadIdx.x, lane = tid & 31, wid = tid >> 5;
    const int b = blockIdx.z, h = blockIdx.y, q0 = blockIdx.x * 128;
    const int arow = lane & 15, acol8 = (lane >> 4) * 8;
    const int g = lane >> 2, lam = lane & 3;
    const uint32_t sb = (uint32_t)__cvta_generic_to_shared(dsm);
    const uint32_t KVB0 = 16384u, KVSZ = 16384u, VOFF = 8192u;
    const uint32_t FQ = 49152u, F0 = 49160u, F1 = 49168u;

    const __half* qtile = g_qf2 + (((size_t)b * 8 + h) * 8 + (q0 >> 7)) * 8192;
    const __half* kbase = g_kf2 + ((size_t)b * 8 + h) * 16 * 4096;
    const __half* vbase = g_vf2 + ((size_t)b * 8 + h) * 16 * 4096;

    if (tid == 0) { mbar_init(sb + FQ, 1); mbar_init(sb + F0, 1); mbar_init(sb + F1, 1); }
    __syncthreads();
    if (tid == 0) {
        mbar_expect(sb + FQ, 16384u);
        bulk_g2s(sb, qtile, 16384u, sb + FQ);
        mbar_expect(sb + F0, 16384u);
        bulk_g2s(sb + KVB0,        kbase,        8192u, sb + F0);
        bulk_g2s(sb + KVB0 + VOFF, vbase,        8192u, sb + F0);
        mbar_expect(sb + F1, 16384u);
        bulk_g2s(sb + KVB0 + KVSZ,        kbase + 4096, 8192u, sb + F1);
        bulk_g2s(sb + KVB0 + KVSZ + VOFF, vbase + 4096, 8192u, sb + F1);
    }
    for (int i = tid; i < LL; i += 256) s_maskAll[i] = g_mask[b * LL + i];

    mbar_wait(sb + FQ, 0u);
    uint32_t qh[4][4];
    {
        int m0w = wid * 16;
#pragma unroll
        for (int ks = 0; ks < 4; ks++) {
            uint32_t off = swz128((uint32_t)(((m0w + arow) << 7) + ((ks * 16 + acol8) << 1)));
            ldsm4(qh[ks][0], qh[ks][1], qh[ks][2], qh[ks][3], sb + off);
        }
    }

    float oacc[8][4] = {};
    float lr0 = 0.f, lr1 = 0.f;   // per-thread partial row sums

    for (int kt = 0; kt < LL / 64; kt++) {
        mbar_wait((kt & 1) ? sb + F1 : sb + F0, (uint32_t)((kt >> 1) & 1));
        const uint32_t kvb = sb + KVB0 + (uint32_t)(kt & 1) * KVSZ;
        const int k0g = kt * 64;

        // S = Q K^T (fp16)
        float sacc[8][4] = {};
#pragma unroll
        for (int ks = 0; ks < 4; ks++) {
#pragma unroll
            for (int jj = 0; jj < 4; jj++) {
                uint32_t bh[4];
                uint32_t off = swz128((uint32_t)(((16 * jj + arow) << 7) + ((ks * 16 + acol8) << 1)));
                ldsm4(bh[0], bh[1], bh[2], bh[3], kvb + off);
                mma16816h(sacc[2*jj],   qh[ks], bh[0], bh[2]);
                mma16816h(sacc[2*jj+1], qh[ks], bh[1], bh[3]);
            }
        }

        // single-pass softmax, fixed zero max
        const float cscale = 0.1803368801f;
        uint32_t ph[8][2];
#pragma unroll
        for (int j = 0; j < 8; j++) {
            int kc = 8 * j + 2 * lam;
            bool k0m = s_maskAll[k0g + kc] != 0, k1m = s_maskAll[k0g + kc + 1] != 0;
            float p0 = k0m ? 0.f : fexp2f(sacc[j][0] * cscale);
            float p1 = k1m ? 0.f : fexp2f(sacc[j][1] * cscale);
            float p2 = k0m ? 0.f : fexp2f(sacc[j][2] * cscale);
            float p3 = k1m ? 0.f : fexp2f(sacc[j][3] * cscale);
            lr0 += p0 + p1; lr1 += p2 + p3;
            ph[j][0] = packh2(p0, p1);
            ph[j][1] = packh2(p2, p3);
        }

        // O += P V (fp16)
#pragma unroll
        for (int s = 0; s < 4; s++) {
            uint32_t pah[4] = { ph[2*s][0], ph[2*s][1], ph[2*s+1][0], ph[2*s+1][1] };
#pragma unroll
            for (int jj = 0; jj < 4; jj++) {
                uint32_t vh[4];
                uint32_t off = swz128((uint32_t)(((16 * s + arow) << 7) + ((jj * 16 + acol8) << 1)));
                ldsm4t(vh[0], vh[1], vh[2], vh[3], kvb + VOFF + off);
                mma16816h(oacc[2*jj],   pah, vh[0], vh[1]);
                mma16816h(oacc[2*jj+1], pah, vh[2], vh[3]);
            }
        }
        __syncthreads();
        if (tid == 0 && kt + 2 < LL / 64) {
            uint32_t full = (kt & 1) ? sb + F1 : sb + F0;
            uint32_t base = sb + KVB0 + (uint32_t)(kt & 1) * KVSZ;
            mbar_expect(full, 16384u);
            bulk_g2s(base,        kbase + (size_t)(kt + 2) * 4096, 8192u, full);
            bulk_g2s(base + VOFF, vbase + (size_t)(kt + 2) * 4096, 8192u, full);
        }
    }

    // one final row-sum reduction across the 4-lane group
    lr0 += __shfl_xor_sync(0xffffffffu, lr0, 1);
    lr0 += __shfl_xor_sync(0xffffffffu, lr0, 2);
    lr1 += __shfl_xor_sync(0xffffffffu, lr1, 1);
    lr1 += __shfl_xor_sync(0xffffffffu, lr1, 2);

    // epilogue -> fp16 tiled ao (row-tile (b*HW+q0)>>7, k-tile h)
    float i0 = 1.f / lr0, i1 = 1.f / lr1;
    int row0 = q0 + wid * 16 + g;
    size_t tbase = ((size_t)b * HW + q0) * HID * 2 + (size_t)h * 16384;
#pragma unroll
    for (int j = 0; j < 8; j++) {
        int cin = 8 * j + 2 * lam;
        uint32_t h0 = packh2(oacc[j][0] * i0, oacc[j][1] * i0);
        uint32_t h1 = packh2(oacc[j][2] * i1, oacc[j][3] * i1);
        uint32_t o0 = swz128((uint32_t)((row0 - q0) * 128 + cin * 2));
        uint32_t o1 = swz128((uint32_t)((row0 - q0 + 8) * 128 + cin * 2));
        *(uint32_t*)((char*)g_ao_f + tbase + o0) = h0;
        *(uint32_t*)((char*)g_ao_f + tbase + o1) = h1;
    }
}

// ---------------------------------------------------------------------------
extern "C" void kernel_launch(void* const* d_in, const int* in_sizes, int n_in,
                              void* d_out, int out_size)
{
    const float* v  = (const float*)d_in[0];
    const float* k  = (const float*)d_in[1];
    const float* q  = (const float*)d_in[2];
    const unsigned char* mask = (const unsigned char*)d_in[3];
    const float* Wv = (const float*)d_in[4];
    const float* bv = (const float*)d_in[5];
    const float* Wk = (const float*)d_in[6];
    const float* bk = (const float*)d_in[7];
    const float* Wq = (const float*)d_in[8];
    const float* bq = (const float*)d_in[9];
    const float* Wm = (const float*)d_in[10];
    const float* bm = (const float*)d_in[11];
    float* out = (float*)d_out;

    const int GEMM_SMEM = 65536 + 16;
    const int ATTN_SMEM = 49152 + 32;
    cudaFuncSetAttribute((const void*)proj_gemm,   cudaFuncAttributeMaxDynamicSharedMemorySize, GEMM_SMEM);
    cudaFuncSetAttribute((const void*)out_gemm,    cudaFuncAttributeMaxDynamicSharedMemorySize, GEMM_SMEM);
    cudaFuncSetAttribute((const void*)attn_kernel, cudaFuncAttributeMaxDynamicSharedMemorySize, ATTN_SMEM);

    fused_pre<<<8736, 256>>>(q, k, v, Wk, Wv, Wq, Wm, mask);
    proj_gemm<<<dim3(HID/128, (BB*LL)/128, 3), 256, GEMM_SMEM>>>(bk, bv, bq);
    attn_kernel<<<dim3(HW/128, NH, BB), 256, ATTN_SMEM>>>();
    out_gemm<<<dim3(HW/128, 512/128, BB), 256, GEMM_SMEM>>>(bm, out);
}

// round 17
// speedup vs baseline: 1.0745x; 1.0745x over previous
#include <cuda_runtime.h>
#include <cuda_bf16.h>
#include <cuda_fp16.h>
#include <math.h>
#include <stdint.h>

#define BB   8
#define LL   1024
#define HW   1024
#define HID  512
#define NH   8
#define DH   64

// fp16 tiled-swizzled GEMM operands: [tile (row>>7)*8 + (k>>6)][128x64 SW128 16KB]
__device__ __half g_kin_f[BB*LL*HID];
__device__ __half g_vin_f[BB*LL*HID];
__device__ __half g_qt_f [BB*HW*HID];
__device__ __half g_wk_f[HID*HID];
__device__ __half g_wv_f[HID*HID];
__device__ __half g_wq_f[HID*HID];
__device__ __half g_wm_f[HID*HID];
__device__ __half g_ao_f[BB*HW*HID];    // tiled (out-proj B operand)
// head-separated swizzled attention operands:
// K/V: [b][h][ltile 0..15][64x64 fp16 SW128 8KB]; Q: [b][h][qtile 0..7][128x64 16KB]
__device__ __half g_kf2[BB*LL*HID];
__device__ __half g_vf2[BB*LL*HID];
__device__ __half g_qf2[BB*HW*HID];
__device__ unsigned char g_mask[BB*LL];

// ---------------- helpers ----------------
__device__ __forceinline__ uint32_t packh2(float a, float b)
{
    __half2 h = __floats2half2_rn(a, b);
    return *reinterpret_cast<uint32_t*>(&h);
}
__device__ __forceinline__ float fexp2f(float x)
{
    x = fmaxf(x, -126.0f);
    int   n = __float2int_rn(x);
    float f = x - (float)n;
    float p = 1.33336498e-3f;
    p = fmaf(p, f, 9.61817007e-3f);
    p = fmaf(p, f, 5.55041087e-2f);
    p = fmaf(p, f, 2.40226507e-1f);
    p = fmaf(p, f, 6.93147181e-1f);
    p = fmaf(p, f, 1.0f);
    return p * __int_as_float((n + 127) << 23);
}
__device__ __forceinline__ void ldsm4(uint32_t& r0, uint32_t& r1, uint32_t& r2, uint32_t& r3, uint32_t a)
{
    asm volatile("ldmatrix.sync.aligned.m8n8.x4.shared.b16 {%0,%1,%2,%3}, [%4];"
                 : "=r"(r0), "=r"(r1), "=r"(r2), "=r"(r3) : "r"(a));
}
__device__ __forceinline__ void ldsm4t(uint32_t& r0, uint32_t& r1, uint32_t& r2, uint32_t& r3, uint32_t a)
{
    asm volatile("ldmatrix.sync.aligned.m8n8.x4.trans.shared.b16 {%0,%1,%2,%3}, [%4];"
                 : "=r"(r0), "=r"(r1), "=r"(r2), "=r"(r3) : "r"(a));
}
__device__ __forceinline__ void mma16816h(float* d, const uint32_t* a, uint32_t b0, uint32_t b1)
{
    asm volatile("mma.sync.aligned.m16n8k16.row.col.f32.f16.f16.f32 "
                 "{%0,%1,%2,%3}, {%4,%5,%6,%7}, {%8,%9}, {%0,%1,%2,%3};"
                 : "+f"(d[0]), "+f"(d[1]), "+f"(d[2]), "+f"(d[3])
                 : "r"(a[0]), "r"(a[1]), "r"(a[2]), "r"(a[3]), "r"(b0), "r"(b1));
}
__device__ __forceinline__ uint32_t swz128(uint32_t o) { return o ^ ((o >> 3) & 0x70); }

__device__ __forceinline__ void mbar_init(uint32_t a, uint32_t c)
{ asm volatile("mbarrier.init.shared.b64 [%0], %1;" :: "r"(a), "r"(c) : "memory"); }
__device__ __forceinline__ void mbar_expect(uint32_t a, uint32_t bytes)
{ asm volatile("mbarrier.arrive.expect_tx.shared.b64 _, [%0], %1;" :: "r"(a), "r"(bytes) : "memory"); }
__device__ __forceinline__ void mbar_wait(uint32_t a, uint32_t par)
{
    asm volatile(
        "{\n\t.reg .pred P;\n"
        "W%=:\n\tmbarrier.try_wait.parity.acquire.cta.shared::cta.b64 P, [%0], %1, 0x989680;\n"
        "\t@P bra.uni D%=;\n\tbra.uni W%=;\nD%=:\n\t}"
        :: "r"(a), "r"(par) : "memory");
}
__device__ __forceinline__ void bulk_g2s(uint32_t dst, const void* src, uint32_t bytes, uint32_t mbar)
{
    asm volatile("cp.async.bulk.shared::cta.global.mbarrier::complete_tx::bytes [%0], [%1], %2, [%3];"
                 :: "r"(dst), "l"(src), "r"(bytes), "r"(mbar) : "memory");
}

// ---------------- fp32 [R][512] -> fp16 tiled-swizzled (core) ----------------
__device__ __forceinline__ void pack_one(const float* in, __half* o, int i)
{
    int row = i >> 6;
    int kc  = (i & 63) * 8;
    const float4* p = (const float4*)(in + (size_t)row * HID + kc);
    float4 a = p[0], b = p[1];
    uint32_t h0 = packh2(a.x, a.y), h1 = packh2(a.z, a.w);
    uint32_t h2 = packh2(b.x, b.y), h3 = packh2(b.z, b.w);
    uint32_t off = swz128((uint32_t)((row & 127) * 128 + (kc & 63) * 2));
    size_t base = ((size_t)(row >> 7) * 8 + (kc >> 6)) * 16384 + off;
    *(uint4*)((char*)o + base) = make_uint4(h0, h1, h2, h3);
}

// ---------------------------------------------------------------------------
// Fused preprocessing (verified R13)
// ---------------------------------------------------------------------------
__global__ __launch_bounds__(256)
void fused_pre(const float* __restrict__ q, const float* __restrict__ k,
               const float* __restrict__ v, const float* __restrict__ Wk,
               const float* __restrict__ Wv, const float* __restrict__ Wq,
               const float* __restrict__ Wm, const unsigned char* __restrict__ m)
{
    const int blk = blockIdx.x, tid = threadIdx.x;
    if (blk < 4096) {
        __shared__ float t[32][33];
        int bx = blk & 31, by = (blk >> 5) & 15, bz = blk >> 9;
        int tx = tid & 31, ty = tid >> 5;
        int hw0 = bx * 32, c0 = by * 32;
        const float* ip = q + ((long)bz * HID + c0) * HW + hw0;
#pragma unroll
        for (int j = 0; j < 32; j += 8)
            t[ty + j][tx] = ip[(long)(ty + j) * HW + tx];
        __syncthreads();
#pragma unroll
        for (int j = 0; j < 32; j += 8) {
            float vv = t[tx][ty + j];
            int rowg = bz * HW + hw0 + ty + j;
            int col  = c0 + tx;
            uint32_t off = swz128((uint32_t)((rowg & 127) * 128 + (col & 63) * 2));
            size_t base = ((size_t)(rowg >> 7) * 8 + (col >> 6)) * 16384 + off;
            *(__half*)((char*)g_qt_f + base) = __float2half_rn(vv);
        }
    } else if (blk < 8192) {
        int bb = blk - 4096;
        int i = (bb & 2047) * 256 + tid;
        if (bb < 2048) pack_one(k, g_kin_f, i);
        else           pack_one(v, g_vin_f, i);
    } else if (blk < 8704) {
        int bb = blk - 8192;
        int i = (bb & 127) * 256 + tid;
        int z = bb >> 7;
        if (z == 0)      pack_one(Wk, g_wk_f, i);
        else if (z == 1) pack_one(Wv, g_wv_f, i);
        else if (z == 2) pack_one(Wq, g_wq_f, i);
        else             pack_one(Wm, g_wm_f, i);
    } else {
        __shared__ int s_wide, s_bytes;
        if (tid == 0) { s_wide = 0; s_bytes = 0; }
        __syncthreads();
        int wide = 0, bytes = 0;
        for (int i = tid; i < BB*LL; i += 256) {
            unsigned char c = m[i];
            if (c > 1) wide = 1;
            else if (c != 0 && (i & 3) != 0) bytes = 1;
        }
        if (wide)  atomicOr(&s_wide, 1);
        if (bytes) atomicOr(&s_bytes, 1);
        __syncthreads();
        const bool is_u8 = (!s_wide) && s_bytes;
        int i = (blk - 8704) * 256 + tid;
        unsigned char vv;
        if (is_u8) vv = (m[i] != 0);
        else       vv = (((const int*)m)[i] != 0);
        g_mask[i] = vv;
    }
}

// ---------------------------------------------------------------------------
// fp16 single-term GEMM mainloop (verified R10-R15).
// ---------------------------------------------------------------------------
__device__ __forceinline__ void gemm_mainloop_h(
    const __half* A, const __half* B, size_t at, size_t bt,
    uint32_t sb, int tid, int lane, int wid, float acc[4][4][4])
{
    const int wm = (wid & 1) * 64, wn = (wid >> 1) * 32;
    const int arow = lane & 15, acol8 = (lane >> 4) * 8;
    const uint32_t F0 = 65536u, F1 = 65544u;

    if (tid == 0) { mbar_init(sb + F0, 1); mbar_init(sb + F1, 1); }
    __syncthreads();
    if (tid == 0) {
        mbar_expect(sb + F0, 32768u);
        bulk_g2s(sb,           A + at * 8192, 16384u, sb + F0);
        bulk_g2s(sb + 16384u,  B + bt * 8192, 16384u, sb + F0);
        mbar_expect(sb + F1, 32768u);
        bulk_g2s(sb + 32768u,  A + (at + 1) * 8192, 16384u, sb + F1);
        bulk_g2s(sb + 49152u,  B + (bt + 1) * 8192, 16384u, sb + F1);
    }
    for (int s = 0; s < 8; s++) {
        mbar_wait((s & 1) ? sb + F1 : sb + F0, (uint32_t)((s >> 1) & 1));
        uint32_t bb = sb + (uint32_t)(s & 1) * 32768u;
#pragma unroll
        for (int ks = 0; ks < 4; ks++) {
            const int kc = ks * 16 + acol8;
            uint32_t ah[4][4];
#pragma unroll
            for (int i = 0; i < 4; i++) {
                uint32_t off = swz128((uint32_t)(((wm + 16 * i + arow) << 7) + (kc << 1)));
                ldsm4(ah[i][0], ah[i][1], ah[i][2], ah[i][3], bb + off);
            }
#pragma unroll
            for (int jj = 0; jj < 2; jj++) {
                uint32_t bh[4];
                uint32_t off = swz128((uint32_t)(((wn + 16 * jj + arow) << 7) + (kc << 1)));
                ldsm4(bh[0], bh[1], bh[2], bh[3], bb + 16384u + off);
#pragma unroll
                for (int i = 0; i < 4; i++) {
                    mma16816h(acc[i][2*jj],   ah[i], bh[0], bh[2]);
                    mma16816h(acc[i][2*jj+1], ah[i], bh[1], bh[3]);
                }
            }
        }
        __syncthreads();
        if (tid == 0 && s + 2 < 8) {
            uint32_t full = (s & 1) ? sb + F1 : sb + F0;
            uint32_t base = sb + (uint32_t)(s & 1) * 32768u;
            mbar_expect(full, 32768u);
            bulk_g2s(base,           A + (at + s + 2) * 8192, 16384u, full);
            bulk_g2s(base + 16384u,  B + (bt + s + 2) * 8192, 16384u, full);
        }
    }
}

// ---- fused k/v/q projections (verified R13) ----
__global__ __launch_bounds__(256, 2)
void proj_gemm(const float* __restrict__ bk, const float* __restrict__ bv,
               const float* __restrict__ bq)
{
    extern __shared__ char smc[];
    const uint32_t sb = (uint32_t)__cvta_generic_to_shared(smc);
    const int tid = threadIdx.x, lane = tid & 31, wid = tid >> 5;
    const int m0 = blockIdx.y * 128, n0 = blockIdx.x * 128, z = blockIdx.z;

    const __half *A, *B;
    const float* bias;
    if (z == 0)      { A = g_kin_f; B = g_wk_f; bias = bk; }
    else if (z == 1) { A = g_vin_f; B = g_wv_f; bias = bv; }
    else             { A = g_qt_f;  B = g_wq_f; bias = bq; }

    float acc[4][4][4] = {};
    gemm_mainloop_h(A, B, (size_t)(m0 >> 7) * 8, (size_t)(n0 >> 7) * 8,
                    sb, tid, lane, wid, acc);

    const int wm = (wid & 1) * 64, wn = (wid >> 1) * 32;
    const int g = lane >> 2, lam = lane & 3;
#pragma unroll
    for (int i = 0; i < 4; i++) {
#pragma unroll
        for (int j = 0; j < 4; j++) {
            int row0 = m0 + wm + 16 * i + g;
            int col  = n0 + wn + 8 * j + 2 * lam;
            float b0 = bias[col], b1 = bias[col + 1];
            uint32_t p0 = packh2(acc[i][j][0] + b0, acc[i][j][1] + b1);
            uint32_t p1 = packh2(acc[i][j][2] + b0, acc[i][j][3] + b1);
            int hh = col >> 6, cin = col & 63;
            if (z < 2) {
                __half* dst = (z == 0) ? g_kf2 : g_vf2;
                int r1 = row0 + 8;
                size_t tb0 = (((size_t)(row0 >> 10) * 8 + hh) * 16 + ((row0 & 1023) >> 6)) * 8192;
                size_t tb1 = (((size_t)(r1 >> 10) * 8 + hh) * 16 + ((r1 & 1023) >> 6)) * 8192;
                *(uint32_t*)((char*)dst + tb0 + swz128((uint32_t)((row0 & 63) * 128 + cin * 2))) = p0;
                *(uint32_t*)((char*)dst + tb1 + swz128((uint32_t)((r1 & 63) * 128 + cin * 2)))   = p1;
            } else {
                int r1 = row0 + 8;
                size_t tb0 = (((size_t)(row0 >> 10) * 8 + hh) * 8 + ((row0 & 1023) >> 7)) * 16384;
                size_t tb1 = (((size_t)(r1 >> 10) * 8 + hh) * 8 + ((r1 & 1023) >> 7)) * 16384;
                *(uint32_t*)((char*)g_qf2 + tb0 + swz128((uint32_t)((row0 & 127) * 128 + cin * 2))) = p0;
                *(uint32_t*)((char*)g_qf2 + tb1 + swz128((uint32_t)((r1 & 127) * 128 + cin * 2)))   = p1;
            }
        }
    }
}

// ---- output projection (verified R13) ----
__global__ __launch_bounds__(256, 2)
void out_gemm(const float* __restrict__ bm, float* __restrict__ out)
{
    extern __shared__ char smc[];
    const uint32_t sb = (uint32_t)__cvta_generic_to_shared(smc);
    const int tid = threadIdx.x, lane = tid & 31, wid = tid >> 5;
    const int m0 = blockIdx.y * 128, n0 = blockIdx.x * 128, z = blockIdx.z;

    float acc[4][4][4] = {};
    gemm_mainloop_h(g_wm_f, g_ao_f,
                    (size_t)(m0 >> 7) * 8, (size_t)((z * HW + n0) >> 7) * 8,
                    sb, tid, lane, wid, acc);

    const int wm = (wid & 1) * 64, wn = (wid >> 1) * 32;
    const int g = lane >> 2, lam = lane & 3;
    float* cfp = out + (size_t)z * 512 * HW;
#pragma unroll
    for (int i = 0; i < 4; i++) {
#pragma unroll
        for (int j = 0; j < 4; j++) {
            int row0 = m0 + wm + 16 * i + g;
            int col  = n0 + wn + 8 * j + 2 * lam;
            float ba = bm[row0], bb2 = bm[row0 + 8];
            float v00 = fmaxf(acc[i][j][0] + ba, 0.f),  v01 = fmaxf(acc[i][j][1] + ba, 0.f);
            float v10 = fmaxf(acc[i][j][2] + bb2, 0.f), v11 = fmaxf(acc[i][j][3] + bb2, 0.f);
            *(float2*)&cfp[(size_t)row0 * HW + col]       = make_float2(v00, v01);
            *(float2*)&cfp[(size_t)(row0 + 8) * HW + col] = make_float2(v10, v11);
        }
    }
}

// ---------------------------------------------------------------------------
// Flash attention: fp16, Br=128, R13 online softmax, 2 CTAs/SM.
// 128 keys per barrier cycle (two 64-key chunks per mbar_wait/sync):
// smem: Q 16KB | 2 x [K0 8K|K1 8K|V0 8K|V1 8K] = 80KB + barriers.
// ---------------------------------------------------------------------------
__global__ __launch_bounds__(256, 2)
void attn_kernel()
{
    extern __shared__ __align__(1024) uint32_t dsm[];
    __shared__ unsigned char s_maskAll[LL];
    const int tid = threadIdx.x, lane = tid & 31, wid = tid >> 5;
    const int b = blockIdx.z, h = blockIdx.y, q0 = blockIdx.x * 128;
    const int arow = lane & 15, acol8 = (lane >> 4) * 8;
    const int g = lane >> 2, lam = lane & 3;
    const uint32_t sb = (uint32_t)__cvta_generic_to_shared(dsm);
    const uint32_t KVB0 = 16384u, KVSZ = 32768u, VOFF = 16384u;
    const uint32_t FQ = 81920u, F0 = 81928u, F1 = 81936u;

    const __half* qtile = g_qf2 + (((size_t)b * 8 + h) * 8 + (q0 >> 7)) * 8192;
    const __half* kbase = g_kf2 + ((size_t)b * 8 + h) * 16 * 4096;
    const __half* vbase = g_vf2 + ((size_t)b * 8 + h) * 16 * 4096;

    if (tid == 0) { mbar_init(sb + FQ, 1); mbar_init(sb + F0, 1); mbar_init(sb + F1, 1); }
    __syncthreads();
    if (tid == 0) {
        mbar_expect(sb + FQ, 16384u);
        bulk_g2s(sb, qtile, 16384u, sb + FQ);
        mbar_expect(sb + F0, 32768u);
        bulk_g2s(sb + KVB0,        kbase,        16384u, sb + F0);
        bulk_g2s(sb + KVB0 + VOFF, vbase,        16384u, sb + F0);
        mbar_expect(sb + F1, 32768u);
        bulk_g2s(sb + KVB0 + KVSZ,        kbase + 8192, 16384u, sb + F1);
        bulk_g2s(sb + KVB0 + KVSZ + VOFF, vbase + 8192, 16384u, sb + F1);
    }
    for (int i = tid; i < LL; i += 256) s_maskAll[i] = g_mask[b * LL + i];

    mbar_wait(sb + FQ, 0u);
    uint32_t qh[4][4];
    {
        int m0w = wid * 16;
#pragma unroll
        for (int ks = 0; ks < 4; ks++) {
            uint32_t off = swz128((uint32_t)(((m0w + arow) << 7) + ((ks * 16 + acol8) << 1)));
            ldsm4(qh[ks][0], qh[ks][1], qh[ks][2], qh[ks][3], sb + off);
        }
    }

    float oacc[8][4] = {};
    float mr0 = -1e30f, mr1 = -1e30f, lr0 = 0.f, lr1 = 0.f;

    for (int kt2 = 0; kt2 < LL / 128; kt2++) {
        mbar_wait((kt2 & 1) ? sb + F1 : sb + F0, (uint32_t)((kt2 >> 1) & 1));
        const uint32_t kvb = sb + KVB0 + (uint32_t)(kt2 & 1) * KVSZ;

#pragma unroll
        for (int c = 0; c < 2; c++) {
            const uint32_t kb = kvb + (uint32_t)c * 8192u;
            const uint32_t vb = kvb + VOFF + (uint32_t)c * 8192u;
            const int k0g = kt2 * 128 + c * 64;

            // S = Q K^T (fp16)
            float sacc[8][4] = {};
#pragma unroll
            for (int ks = 0; ks < 4; ks++) {
#pragma unroll
                for (int jj = 0; jj < 4; jj++) {
                    uint32_t bh[4];
                    uint32_t off = swz128((uint32_t)(((16 * jj + arow) << 7) + ((ks * 16 + acol8) << 1)));
                    ldsm4(bh[0], bh[1], bh[2], bh[3], kb + off);
                    mma16816h(sacc[2*jj],   qh[ks], bh[0], bh[2]);
                    mma16816h(sacc[2*jj+1], qh[ks], bh[1], bh[3]);
                }
            }

            // online softmax (R13-exact)
            const float cscale = 0.1803368801f;
            float mn0 = mr0, mn1 = mr1;
#pragma unroll
            for (int j = 0; j < 8; j++) {
                int kc = 8 * j + 2 * lam;
                bool k0m = s_maskAll[k0g + kc] != 0, k1m = s_maskAll[k0g + kc + 1] != 0;
                sacc[j][0] = k0m ? -1e9f : sacc[j][0] * cscale;
                sacc[j][1] = k1m ? -1e9f : sacc[j][1] * cscale;
                sacc[j][2] = k0m ? -1e9f : sacc[j][2] * cscale;
                sacc[j][3] = k1m ? -1e9f : sacc[j][3] * cscale;
                mn0 = fmaxf(mn0, fmaxf(sacc[j][0], sacc[j][1]));
                mn1 = fmaxf(mn1, fmaxf(sacc[j][2], sacc[j][3]));
            }
            mn0 = fmaxf(mn0, __shfl_xor_sync(0xffffffffu, mn0, 1));
            mn0 = fmaxf(mn0, __shfl_xor_sync(0xffffffffu, mn0, 2));
            mn1 = fmaxf(mn1, __shfl_xor_sync(0xffffffffu, mn1, 1));
            mn1 = fmaxf(mn1, __shfl_xor_sync(0xffffffffu, mn1, 2));
            float cs0 = fexp2f(mr0 - mn0), cs1 = fexp2f(mr1 - mn1);
            mr0 = mn0; mr1 = mn1;
            float rs0 = 0.f, rs1 = 0.f;
            uint32_t ph[8][2];
#pragma unroll
            for (int j = 0; j < 8; j++) {
                float p0 = fexp2f(sacc[j][0] - mn0);
                float p1 = fexp2f(sacc[j][1] - mn0);
                float p2 = fexp2f(sacc[j][2] - mn1);
                float p3 = fexp2f(sacc[j][3] - mn1);
                rs0 += p0 + p1; rs1 += p2 + p3;
                ph[j][0] = packh2(p0, p1);
                ph[j][1] = packh2(p2, p3);
            }
            rs0 += __shfl_xor_sync(0xffffffffu, rs0, 1);
            rs0 += __shfl_xor_sync(0xffffffffu, rs0, 2);
            rs1 += __shfl_xor_sync(0xffffffffu, rs1, 1);
            rs1 += __shfl_xor_sync(0xffffffffu, rs1, 2);
            lr0 = lr0 * cs0 + rs0;
            lr1 = lr1 * cs1 + rs1;
#pragma unroll
            for (int j = 0; j < 8; j++) {
                oacc[j][0] *= cs0; oacc[j][1] *= cs0;
                oacc[j][2] *= cs1; oacc[j][3] *= cs1;
            }

            // O += P V (fp16)
#pragma unroll
            for (int s = 0; s < 4; s++) {
                uint32_t pah[4] = { ph[2*s][0], ph[2*s][1], ph[2*s+1][0], ph[2*s+1][1] };
#pragma unroll
                for (int jj = 0; jj < 4; jj++) {
                    uint32_t vh[4];
                    uint32_t off = swz128((uint32_t)(((16 * s + arow) << 7) + ((jj * 16 + acol8) << 1)));
                    ldsm4t(vh[0], vh[1], vh[2], vh[3], vb + off);
                    mma16816h(oacc[2*jj],   pah, vh[0], vh[1]);
                    mma16816h(oacc[2*jj+1], pah, vh[2], vh[3]);
                }
            }
        }
        __syncthreads();
        if (tid == 0 && kt2 + 2 < LL / 128) {
            uint32_t full = (kt2 & 1) ? sb + F1 : sb + F0;
            uint32_t base = sb + KVB0 + (uint32_t)(kt2 & 1) * KVSZ;
            mbar_expect(full, 32768u);
            bulk_g2s(base,        kbase + (size_t)(kt2 + 2) * 8192, 16384u, full);
            bulk_g2s(base + VOFF, vbase + (size_t)(kt2 + 2) * 8192, 16384u, full);
        }
    }

    // epilogue -> fp16 tiled ao (row-tile (b*HW+q0)>>7, k-tile h)
    float i0 = 1.f / lr0, i1 = 1.f / lr1;
    int row0 = q0 + wid * 16 + g;
    size_t tbase = ((size_t)b * HW + q0) * HID * 2 + (size_t)h * 16384;
#pragma unroll
    for (int j = 0; j < 8; j++) {
        int cin = 8 * j + 2 * lam;
        uint32_t h0 = packh2(oacc[j][0] * i0, oacc[j][1] * i0);
        uint32_t h1 = packh2(oacc[j][2] * i1, oacc[j][3] * i1);
        uint32_t o0 = swz128((uint32_t)((row0 - q0) * 128 + cin * 2));
        uint32_t o1 = swz128((uint32_t)((row0 - q0 + 8) * 128 + cin * 2));
        *(uint32_t*)((char*)g_ao_f + tbase + o0) = h0;
        *(uint32_t*)((char*)g_ao_f + tbase + o1) = h1;
    }
}

// ---------------------------------------------------------------------------
extern "C" void kernel_launch(void* const* d_in, const int* in_sizes, int n_in,
                              void* d_out, int out_size)
{
    const float* v  = (const float*)d_in[0];
    const float* k  = (const float*)d_in[1];
    const float* q  = (const float*)d_in[2];
    const unsigned char* mask = (const unsigned char*)d_in[3];
    const float* Wv = (const float*)d_in[4];
    const float* bv = (const float*)d_in[5];
    const float* Wk = (const float*)d_in[6];
    const float* bk = (const float*)d_in[7];
    const float* Wq = (const float*)d_in[8];
    const float* bq = (const float*)d_in[9];
    const float* Wm = (const float*)d_in[10];
    const float* bm = (const float*)d_in[11];
    float* out = (float*)d_out;

    const int GEMM_SMEM = 65536 + 16;
    const int ATTN_SMEM = 81920 + 32;
    cudaFuncSetAttribute((const void*)proj_gemm,   cudaFuncAttributeMaxDynamicSharedMemorySize, GEMM_SMEM);
    cudaFuncSetAttribute((const void*)out_gemm,    cudaFuncAttributeMaxDynamicSharedMemorySize, GEMM_SMEM);
    cudaFuncSetAttribute((const void*)attn_kernel, cudaFuncAttributeMaxDynamicSharedMemorySize, ATTN_SMEM);

    fused_pre<<<8736, 256>>>(q, k, v, Wk, Wv, Wq, Wm, mask);
    proj_gemm<<<dim3(HID/128, (BB*LL)/128, 3), 256, GEMM_SMEM>>>(bk, bv, bq);
    attn_kernel<<<dim3(HW/128, NH, BB), 256, ATTN_SMEM>>>();
    out_gemm<<<dim3(HW/128, 512/128, BB), 256, GEMM_SMEM>>>(bm, out);
}